// round 1
// baseline (speedup 1.0000x reference)
#include <cuda_runtime.h>

#define TPB 256
static constexpr int Bn  = 1024;
static constexpr int Pn  = 100;
static constexpr int Nn  = 101;
static constexpr int EMBn = 128;
static constexpr int Hn  = 8;
static constexpr int DKn = 16;
static constexpr int LDSR = 132;   // smem row stride in floats (conflict-free float4 rows)

// smem layout (floats)
static constexpr int OFF_N = 0;                       // nodes   [101][132]
static constexpr int OFF_K = 101 * LDSR;              // cat/K/mh[101][132]
static constexpr int OFF_V = 2 * 101 * LDSR;          // V       [101][132]
static constexpr int OFF_Q = 3 * 101 * LDSR;          // Q/out   [100][132]
static constexpr int OFF_B = OFF_Q + 100 * LDSR;      // B tile  [16][132]
static constexpr int SMEM_FLOATS = OFF_B + 16 * LDSR;
static constexpr int SMEM_BYTES  = SMEM_FLOATS * 4;   // 221232 B < 227 KB

__device__ __forceinline__ float f4c(const float4& v, int t) {
    return t == 0 ? v.x : t == 1 ? v.y : t == 2 ? v.z : v.w;
}

__device__ __forceinline__ float tanh10(float x) {
    x = fminf(fmaxf(x, -20.f), 20.f);
    float t = __expf(2.f * x);
    return 10.f * (t - 1.f) / (t + 1.f);
}

// C[M,128] = A[M,K] @ B[K,128] (+bias), A/C in smem (stride LDSR), B from gmem via sB tile.
__device__ __forceinline__ void gemm_tile(
    const float* __restrict__ sA, int M, int K,
    const float* __restrict__ gB,
    float* __restrict__ sC,
    const float* __restrict__ bias,
    float* __restrict__ sB)
{
    const int tid = threadIdx.x;
    const int tx = tid & 15;
    const int ty = tid >> 4;

    float acc[8][8];
#pragma unroll
    for (int i = 0; i < 8; i++)
#pragma unroll
        for (int j = 0; j < 8; j++) acc[i][j] = 0.f;

    int rows[8], rc[8];
#pragma unroll
    for (int i = 0; i < 4; i++) { rows[i] = ty * 4 + i; rows[4 + i] = 64 + ty * 4 + i; }
#pragma unroll
    for (int i = 0; i < 8; i++) rc[i] = rows[i] < M ? rows[i] : (M - 1);

    for (int k0 = 0; k0 < K; k0 += 16) {
        const int kc = min(16, K - k0);
        __syncthreads();
        for (int i = tid; i < kc * 32; i += TPB) {
            int kk = i >> 5, c = (i & 31) << 2;
            *(float4*)&sB[kk * LDSR + c] = *(const float4*)&gB[(k0 + kk) * 128 + c];
        }
        __syncthreads();
#pragma unroll 2
        for (int kk = 0; kk < kc; kk += 4) {
            float4 a[8];
#pragma unroll
            for (int i = 0; i < 8; i++)
                a[i] = *(const float4*)&sA[rc[i] * LDSR + k0 + kk];
            float4 bl[4], bh[4];
#pragma unroll
            for (int t = 0; t < 4; t++) {
                bl[t] = *(const float4*)&sB[(kk + t) * LDSR + tx * 4];
                bh[t] = *(const float4*)&sB[(kk + t) * LDSR + 64 + tx * 4];
            }
#pragma unroll
            for (int t = 0; t < 4; t++) {
#pragma unroll
                for (int i = 0; i < 8; i++) {
                    float av = f4c(a[i], t);
                    acc[i][0] += av * bl[t].x; acc[i][1] += av * bl[t].y;
                    acc[i][2] += av * bl[t].z; acc[i][3] += av * bl[t].w;
                    acc[i][4] += av * bh[t].x; acc[i][5] += av * bh[t].y;
                    acc[i][6] += av * bh[t].z; acc[i][7] += av * bh[t].w;
                }
            }
        }
    }
    __syncthreads();

    float4 b0 = make_float4(0, 0, 0, 0), b1 = b0;
    if (bias) {
        b0 = *(const float4*)&bias[tx * 4];
        b1 = *(const float4*)&bias[64 + tx * 4];
    }
#pragma unroll
    for (int i = 0; i < 8; i++) {
        if (rows[i] < M) {
            *(float4*)&sC[rows[i] * LDSR + tx * 4] =
                make_float4(acc[i][0] + b0.x, acc[i][1] + b0.y,
                            acc[i][2] + b0.z, acc[i][3] + b0.w);
            *(float4*)&sC[rows[i] * LDSR + 64 + tx * 4] =
                make_float4(acc[i][4] + b1.x, acc[i][5] + b1.y,
                            acc[i][6] + b1.z, acc[i][7] + b1.w);
        }
    }
    __syncthreads();
}

extern __shared__ float smem[];

__global__ __launch_bounds__(TPB, 1)
void vrp_decoder_kernel(
    const float* __restrict__ eln,   // [B,P,EMB]
    const float* __restrict__ load_, // [B,P]
    const float* __restrict__ time_, // [B,P]
    const float* __restrict__ len_,  // [B,P]
    const float* __restrict__ ropen, // [B,P]
    const float* __restrict__ mask,  // [B,P,N]
    const float* __restrict__ nodes, // [B,N,EMB]
    const float* __restrict__ Wq,    // [132,128]
    const float* __restrict__ Wk,    // [128,128]
    const float* __restrict__ Wv,    // [128,128]
    const float* __restrict__ Wc,    // [128,128]
    const float* __restrict__ bc,    // [128]
    float* __restrict__ out)         // [B,P,N]
{
    const int b = blockIdx.x;
    const int tid = threadIdx.x;
    float* sN = smem + OFF_N;
    float* sK = smem + OFF_K;   // cat -> K -> mh
    float* sV = smem + OFF_V;
    float* sQ = smem + OFF_Q;   // Q -> out_concat
    float* sB = smem + OFF_B;

    // ---- load nodes into smem (read from HBM exactly once) ----
    const float* gN = nodes + (size_t)b * Nn * EMBn;
    for (int i = tid; i < Nn * (EMBn / 4); i += TPB) {
        int r = i >> 5, c = (i & 31) << 2;
        *(float4*)&sN[r * LDSR + c] = *(const float4*)&gN[r * EMBn + c];
    }
    // ---- build input_cat [100][132] in sK ----
    const float* gE = eln + (size_t)b * Pn * EMBn;
    for (int i = tid; i < Pn * (EMBn / 4); i += TPB) {
        int r = i >> 5, c = (i & 31) << 2;
        *(float4*)&sK[r * LDSR + c] = *(const float4*)&gE[r * EMBn + c];
    }
    for (int r = tid; r < Pn; r += TPB) {
        sK[r * LDSR + 128] = load_[b * Pn + r];
        sK[r * LDSR + 129] = time_[b * Pn + r];
        sK[r * LDSR + 130] = len_[b * Pn + r];
        sK[r * LDSR + 131] = ropen[b * Pn + r];
    }
    __syncthreads();

    // ---- projections ----
    gemm_tile(sK, Pn, 132, Wq, sQ, nullptr, sB);   // Q = cat @ Wq (reads sK before overwrite)
    gemm_tile(sN, Nn, 128, Wk, sK, nullptr, sB);   // K = nodes @ Wk
    gemm_tile(sN, Nn, 128, Wv, sV, nullptr, sB);   // V = nodes @ Wv

    // ---- attention: warp per row-pair, softmax over N, out written into sQ ----
    const float* gM = mask + (size_t)b * Pn * Nn;
    const int warp = tid >> 5, lane = tid & 31;

    for (int pi = warp; pi < Pn / 2; pi += 8) {
        const int p0 = 2 * pi, p1 = p0 + 1;
        float m0[4], m1[4];
        int nc[4], nn[4];
#pragma unroll
        for (int j = 0; j < 4; j++) {
            int n = lane + 32 * j;
            nn[j] = n;
            nc[j] = n < Nn ? n : 0;
            m0[j] = n < Nn ? gM[p0 * Nn + n] : -INFINITY;
            m1[j] = n < Nn ? gM[p1 * Nn + n] : -INFINITY;
        }
        for (int h = 0; h < Hn; h++) {
            const int ho = h * DKn;
            float4 q0[4], q1[4];
#pragma unroll
            for (int t = 0; t < 4; t++) {
                q0[t] = *(const float4*)&sQ[p0 * LDSR + ho + 4 * t];
                q1[t] = *(const float4*)&sQ[p1 * LDSR + ho + 4 * t];
            }
            float s0[4], s1[4];
#pragma unroll
            for (int j = 0; j < 4; j++) {
                const float* kr = &sK[nc[j] * LDSR + ho];
                float a0 = 0.f, a1 = 0.f;
#pragma unroll
                for (int t = 0; t < 4; t++) {
                    float4 kv = *(const float4*)&kr[4 * t];
                    a0 += q0[t].x * kv.x + q0[t].y * kv.y + q0[t].z * kv.z + q0[t].w * kv.w;
                    a1 += q1[t].x * kv.x + q1[t].y * kv.y + q1[t].z * kv.z + q1[t].w * kv.w;
                }
                s0[j] = a0 * 0.25f + m0[j];
                s1[j] = a1 * 0.25f + m1[j];
            }
            // softmax over n (warp-wide)
            float mx0 = fmaxf(fmaxf(s0[0], s0[1]), fmaxf(s0[2], s0[3]));
            float mx1 = fmaxf(fmaxf(s1[0], s1[1]), fmaxf(s1[2], s1[3]));
#pragma unroll
            for (int off = 16; off; off >>= 1) {
                mx0 = fmaxf(mx0, __shfl_xor_sync(0xffffffffu, mx0, off));
                mx1 = fmaxf(mx1, __shfl_xor_sync(0xffffffffu, mx1, off));
            }
            float w0[4], w1[4], sum0 = 0.f, sum1 = 0.f;
#pragma unroll
            for (int j = 0; j < 4; j++) {
                w0[j] = __expf(s0[j] - mx0); sum0 += w0[j];
                w1[j] = __expf(s1[j] - mx1); sum1 += w1[j];
            }
#pragma unroll
            for (int off = 16; off; off >>= 1) {
                sum0 += __shfl_xor_sync(0xffffffffu, sum0, off);
                sum1 += __shfl_xor_sync(0xffffffffu, sum1, off);
            }
            const float inv0 = 1.f / sum0, inv1 = 1.f / sum1;
#pragma unroll
            for (int j = 0; j < 4; j++) { w0[j] *= inv0; w1[j] *= inv1; }

            float o0[16], o1[16];
#pragma unroll
            for (int d = 0; d < 16; d++) { o0[d] = 0.f; o1[d] = 0.f; }
#pragma unroll
            for (int j = 0; j < 4; j++) {
                const float* vr = &sV[nc[j] * LDSR + ho];
#pragma unroll
                for (int t = 0; t < 4; t++) {
                    float4 vv = *(const float4*)&vr[4 * t];
                    o0[4 * t + 0] += w0[j] * vv.x; o0[4 * t + 1] += w0[j] * vv.y;
                    o0[4 * t + 2] += w0[j] * vv.z; o0[4 * t + 3] += w0[j] * vv.w;
                    o1[4 * t + 0] += w1[j] * vv.x; o1[4 * t + 1] += w1[j] * vv.y;
                    o1[4 * t + 2] += w1[j] * vv.z; o1[4 * t + 3] += w1[j] * vv.w;
                }
            }
#pragma unroll
            for (int off = 16; off; off >>= 1) {
#pragma unroll
                for (int d = 0; d < 16; d++) {
                    o0[d] += __shfl_xor_sync(0xffffffffu, o0[d], off);
                    o1[d] += __shfl_xor_sync(0xffffffffu, o1[d], off);
                }
            }
            if (lane == 0) {
#pragma unroll
                for (int t = 0; t < 4; t++) {
                    *(float4*)&sQ[p0 * LDSR + ho + 4 * t] =
                        make_float4(o0[4 * t], o0[4 * t + 1], o0[4 * t + 2], o0[4 * t + 3]);
                    *(float4*)&sQ[p1 * LDSR + ho + 4 * t] =
                        make_float4(o1[4 * t], o1[4 * t + 1], o1[4 * t + 2], o1[4 * t + 3]);
                }
            }
        }
    }
    __syncthreads();

    // ---- mh = out_concat @ Wc + bc  (into sK; K matrix is dead) ----
    gemm_tile(sQ, Pn, 128, Wc, sK, bc, sB);

    // ---- score2 = clip*tanh(mh @ nodes^T / sqrt(EMB)) + mask; softmax; store probs ----
    const float INV_SQRT_EMB = 0.08838834764831843f;  // 1/sqrt(128)
    float* gOut = out + (size_t)b * Pn * Nn;

    for (int pi = warp; pi < Pn / 2; pi += 8) {
        const int p0 = 2 * pi, p1 = p0 + 1;
        float m0[4], m1[4];
        int nc[4], nn[4];
#pragma unroll
        for (int j = 0; j < 4; j++) {
            int n = lane + 32 * j;
            nn[j] = n;
            nc[j] = n < Nn ? n : 0;
            m0[j] = n < Nn ? gM[p0 * Nn + n] : -INFINITY;
            m1[j] = n < Nn ? gM[p1 * Nn + n] : -INFINITY;
        }
        float d0[4] = {0, 0, 0, 0}, d1[4] = {0, 0, 0, 0};
        for (int e = 0; e < EMBn; e += 4) {
            float4 a0 = *(const float4*)&sK[p0 * LDSR + e];
            float4 a1 = *(const float4*)&sK[p1 * LDSR + e];
#pragma unroll
            for (int j = 0; j < 4; j++) {
                float4 nv = *(const float4*)&sN[nc[j] * LDSR + e];
                d0[j] += a0.x * nv.x + a0.y * nv.y + a0.z * nv.z + a0.w * nv.w;
                d1[j] += a1.x * nv.x + a1.y * nv.y + a1.z * nv.z + a1.w * nv.w;
            }
        }
        float s0[4], s1[4];
#pragma unroll
        for (int j = 0; j < 4; j++) {
            s0[j] = (nn[j] < Nn) ? tanh10(d0[j] * INV_SQRT_EMB) + m0[j] : -INFINITY;
            s1[j] = (nn[j] < Nn) ? tanh10(d1[j] * INV_SQRT_EMB) + m1[j] : -INFINITY;
        }
        float mx0 = fmaxf(fmaxf(s0[0], s0[1]), fmaxf(s0[2], s0[3]));
        float mx1 = fmaxf(fmaxf(s1[0], s1[1]), fmaxf(s1[2], s1[3]));
#pragma unroll
        for (int off = 16; off; off >>= 1) {
            mx0 = fmaxf(mx0, __shfl_xor_sync(0xffffffffu, mx0, off));
            mx1 = fmaxf(mx1, __shfl_xor_sync(0xffffffffu, mx1, off));
        }
        float w0[4], w1[4], sum0 = 0.f, sum1 = 0.f;
#pragma unroll
        for (int j = 0; j < 4; j++) {
            w0[j] = __expf(s0[j] - mx0); sum0 += w0[j];
            w1[j] = __expf(s1[j] - mx1); sum1 += w1[j];
        }
#pragma unroll
        for (int off = 16; off; off >>= 1) {
            sum0 += __shfl_xor_sync(0xffffffffu, sum0, off);
            sum1 += __shfl_xor_sync(0xffffffffu, sum1, off);
        }
        const float inv0 = 1.f / sum0, inv1 = 1.f / sum1;
#pragma unroll
        for (int j = 0; j < 4; j++) {
            if (nn[j] < Nn) {
                gOut[p0 * Nn + nn[j]] = w0[j] * inv0;
                gOut[p1 * Nn + nn[j]] = w1[j] * inv1;
            }
        }
    }
}

extern "C" void kernel_launch(void* const* d_in, const int* in_sizes, int n_in,
                              void* d_out, int out_size) {
    const float* eln   = (const float*)d_in[0];
    const float* load_ = (const float*)d_in[1];
    const float* time_ = (const float*)d_in[2];
    const float* len_  = (const float*)d_in[3];
    const float* ropen = (const float*)d_in[4];
    const float* mask  = (const float*)d_in[5];
    const float* nodes = (const float*)d_in[6];
    const float* Wq    = (const float*)d_in[7];
    const float* Wk    = (const float*)d_in[8];
    const float* Wv    = (const float*)d_in[9];
    const float* Wc    = (const float*)d_in[10];
    const float* bc    = (const float*)d_in[11];
    float* out = (float*)d_out;

    cudaFuncSetAttribute(vrp_decoder_kernel,
                         cudaFuncAttributeMaxDynamicSharedMemorySize, SMEM_BYTES);
    vrp_decoder_kernel<<<Bn, TPB, SMEM_BYTES>>>(
        eln, load_, time_, len_, ropen, mask, nodes, Wq, Wk, Wv, Wc, bc, out);
}

// round 2
// speedup vs baseline: 1.3079x; 1.3079x over previous
#include <cuda_runtime.h>

#define TPB 512
static constexpr int Bn  = 1024;
static constexpr int Pn  = 100;
static constexpr int Nn  = 101;
static constexpr int EMBn = 128;
static constexpr int Hn  = 8;
static constexpr int DKn = 16;
static constexpr int LDSR = 132;   // smem row stride in floats (conflict-free float4 rows)

// smem layout (floats)
static constexpr int OFF_N = 0;                       // nodes   [101][132]
static constexpr int OFF_K = 101 * LDSR;              // cat/K/mh[101][132]
static constexpr int OFF_V = 2 * 101 * LDSR;          // V       [101][132]
static constexpr int OFF_Q = 3 * 101 * LDSR;          // Q/out   [100][132]
static constexpr int OFF_B = OFF_Q + 100 * LDSR;      // B tile  [16][132]
static constexpr int SMEM_FLOATS = OFF_B + 16 * LDSR;
static constexpr int SMEM_BYTES  = SMEM_FLOATS * 4;   // 221232 B < 227 KB

__device__ __forceinline__ float f4c(const float4& v, int t) {
    return t == 0 ? v.x : t == 1 ? v.y : t == 2 ? v.z : v.w;
}

__device__ __forceinline__ float tanh10(float x) {
    x = fminf(fmaxf(x, -20.f), 20.f);
    float t = __expf(2.f * x);
    return 10.f * (t - 1.f) / (t + 1.f);
}

// C[M,128] = A[M,K] @ B[K,128] (+bias). A/C in smem (stride LDSR), B from gmem
// staged through sB. 512 threads, 8x4 microtile per thread.
__device__ __forceinline__ void gemm_tile(
    const float* __restrict__ sA, int M, int K,
    const float* __restrict__ gB,
    float* __restrict__ sC,
    const float* __restrict__ bias,
    float* __restrict__ sB)
{
    const int tid = threadIdx.x;
    const int tx = tid & 31;   // col group: cols tx*4 .. tx*4+3
    const int ty = tid >> 5;   // 0..15 row group

    float acc[8][4];
#pragma unroll
    for (int i = 0; i < 8; i++)
#pragma unroll
        for (int j = 0; j < 4; j++) acc[i][j] = 0.f;

    int rows[8], rc[8];
#pragma unroll
    for (int i = 0; i < 4; i++) { rows[i] = ty * 4 + i; rows[4 + i] = 64 + ty * 4 + i; }
#pragma unroll
    for (int i = 0; i < 8; i++) rc[i] = rows[i] < M ? rows[i] : (M - 1);

    for (int k0 = 0; k0 < K; k0 += 16) {
        const int kc = min(16, K - k0);
        __syncthreads();
        for (int i = tid; i < kc * 32; i += TPB) {
            int kk = i >> 5, c = (i & 31) << 2;
            *(float4*)&sB[kk * LDSR + c] = *(const float4*)&gB[(k0 + kk) * 128 + c];
        }
        __syncthreads();
#pragma unroll
        for (int kk = 0; kk < 16; kk += 4) {
            if (kk >= kc) break;
            float4 a[8];
#pragma unroll
            for (int i = 0; i < 8; i++)
                a[i] = *(const float4*)&sA[rc[i] * LDSR + k0 + kk];
            float4 bv[4];
#pragma unroll
            for (int t = 0; t < 4; t++)
                bv[t] = *(const float4*)&sB[(kk + t) * LDSR + tx * 4];
#pragma unroll
            for (int t = 0; t < 4; t++) {
#pragma unroll
                for (int i = 0; i < 8; i++) {
                    float av = f4c(a[i], t);
                    acc[i][0] += av * bv[t].x; acc[i][1] += av * bv[t].y;
                    acc[i][2] += av * bv[t].z; acc[i][3] += av * bv[t].w;
                }
            }
        }
    }
    __syncthreads();

    float4 b0 = make_float4(0, 0, 0, 0);
    if (bias) b0 = *(const float4*)&bias[tx * 4];
#pragma unroll
    for (int i = 0; i < 8; i++) {
        if (rows[i] < M) {
            *(float4*)&sC[rows[i] * LDSR + tx * 4] =
                make_float4(acc[i][0] + b0.x, acc[i][1] + b0.y,
                            acc[i][2] + b0.z, acc[i][3] + b0.w);
        }
    }
    __syncthreads();
}

extern __shared__ float smem[];

__global__ __launch_bounds__(TPB, 1)
void vrp_decoder_kernel(
    const float* __restrict__ eln,   // [B,P,EMB]
    const float* __restrict__ load_, // [B,P]
    const float* __restrict__ time_, // [B,P]
    const float* __restrict__ len_,  // [B,P]
    const float* __restrict__ ropen, // [B,P]
    const float* __restrict__ mask,  // [B,P,N]
    const float* __restrict__ nodes, // [B,N,EMB]
    const float* __restrict__ Wq,    // [132,128]
    const float* __restrict__ Wk,    // [128,128]
    const float* __restrict__ Wv,    // [128,128]
    const float* __restrict__ Wc,    // [128,128]
    const float* __restrict__ bc,    // [128]
    float* __restrict__ out)         // [B,P,N]
{
    const int b = blockIdx.x;
    const int tid = threadIdx.x;
    float* sN = smem + OFF_N;
    float* sK = smem + OFF_K;   // cat -> K -> mh
    float* sV = smem + OFF_V;
    float* sQ = smem + OFF_Q;   // Q -> out_concat
    float* sB = smem + OFF_B;

    // ---- load nodes into smem (read from HBM exactly once) ----
    const float* gN = nodes + (size_t)b * Nn * EMBn;
    for (int i = tid; i < Nn * (EMBn / 4); i += TPB) {
        int r = i >> 5, c = (i & 31) << 2;
        *(float4*)&sN[r * LDSR + c] = *(const float4*)&gN[r * EMBn + c];
    }
    // ---- build input_cat [100][132] in sK ----
    const float* gE = eln + (size_t)b * Pn * EMBn;
    for (int i = tid; i < Pn * (EMBn / 4); i += TPB) {
        int r = i >> 5, c = (i & 31) << 2;
        *(float4*)&sK[r * LDSR + c] = *(const float4*)&gE[r * EMBn + c];
    }
    for (int r = tid; r < Pn; r += TPB) {
        sK[r * LDSR + 128] = load_[b * Pn + r];
        sK[r * LDSR + 129] = time_[b * Pn + r];
        sK[r * LDSR + 130] = len_[b * Pn + r];
        sK[r * LDSR + 131] = ropen[b * Pn + r];
    }
    __syncthreads();

    // ---- projections ----
    gemm_tile(sK, Pn, 132, Wq, sQ, nullptr, sB);   // Q = cat @ Wq (reads sK first)
    gemm_tile(sN, Nn, 128, Wk, sK, nullptr, sB);   // K = nodes @ Wk
    gemm_tile(sN, Nn, 128, Wv, sV, nullptr, sB);   // V = nodes @ Wv

    // ---- attention: warp per row-pair; softmax over N; out -> sQ ----
    const float* gM = mask + (size_t)b * Pn * Nn;
    const int warp = tid >> 5, lane = tid & 31;
    const int NWARP = TPB / 32;

    for (int pi = warp; pi < Pn / 2; pi += NWARP) {
        const int p0 = 2 * pi, p1 = p0 + 1;
        float m0[4], m1[4];
        int nc[4];
#pragma unroll
        for (int j = 0; j < 4; j++) {
            int n = lane + 32 * j;
            nc[j] = n < Nn ? n : 0;
            m0[j] = n < Nn ? gM[p0 * Nn + n] : -INFINITY;
            m1[j] = n < Nn ? gM[p1 * Nn + n] : -INFINITY;
        }
        for (int h = 0; h < Hn; h++) {
            const int ho = h * DKn;
            float4 q0[4], q1[4];
#pragma unroll
            for (int t = 0; t < 4; t++) {
                q0[t] = *(const float4*)&sQ[p0 * LDSR + ho + 4 * t];
                q1[t] = *(const float4*)&sQ[p1 * LDSR + ho + 4 * t];
            }
            float s0[4], s1[4];
#pragma unroll
            for (int j = 0; j < 4; j++) {
                const float* kr = &sK[nc[j] * LDSR + ho];
                float a0 = 0.f, a1 = 0.f;
#pragma unroll
                for (int t = 0; t < 4; t++) {
                    float4 kv = *(const float4*)&kr[4 * t];
                    a0 += q0[t].x * kv.x + q0[t].y * kv.y + q0[t].z * kv.z + q0[t].w * kv.w;
                    a1 += q1[t].x * kv.x + q1[t].y * kv.y + q1[t].z * kv.z + q1[t].w * kv.w;
                }
                s0[j] = a0 * 0.25f + m0[j];
                s1[j] = a1 * 0.25f + m1[j];
            }
            // softmax over n (warp-wide)
            float mx0 = fmaxf(fmaxf(s0[0], s0[1]), fmaxf(s0[2], s0[3]));
            float mx1 = fmaxf(fmaxf(s1[0], s1[1]), fmaxf(s1[2], s1[3]));
#pragma unroll
            for (int off = 16; off; off >>= 1) {
                mx0 = fmaxf(mx0, __shfl_xor_sync(0xffffffffu, mx0, off));
                mx1 = fmaxf(mx1, __shfl_xor_sync(0xffffffffu, mx1, off));
            }
            float w0[4], w1[4], sum0 = 0.f, sum1 = 0.f;
#pragma unroll
            for (int j = 0; j < 4; j++) {
                w0[j] = __expf(s0[j] - mx0); sum0 += w0[j];
                w1[j] = __expf(s1[j] - mx1); sum1 += w1[j];
            }
#pragma unroll
            for (int off = 16; off; off >>= 1) {
                sum0 += __shfl_xor_sync(0xffffffffu, sum0, off);
                sum1 += __shfl_xor_sync(0xffffffffu, sum1, off);
            }
            const float inv0 = 1.f / sum0, inv1 = 1.f / sum1;
#pragma unroll
            for (int j = 0; j < 4; j++) { w0[j] *= inv0; w1[j] *= inv1; }

            // v[0..15] = out(p0, d), v[16..31] = out(p1, d), per-lane partials
            float v[32];
#pragma unroll
            for (int d = 0; d < 32; d++) v[d] = 0.f;
#pragma unroll
            for (int j = 0; j < 4; j++) {
                const float* vr = &sV[nc[j] * LDSR + ho];
#pragma unroll
                for (int t = 0; t < 4; t++) {
                    float4 vv = *(const float4*)&vr[4 * t];
                    v[4 * t + 0]  += w0[j] * vv.x; v[4 * t + 1]  += w0[j] * vv.y;
                    v[4 * t + 2]  += w0[j] * vv.z; v[4 * t + 3]  += w0[j] * vv.w;
                    v[16 + 4 * t] += w1[j] * vv.x; v[17 + 4 * t] += w1[j] * vv.y;
                    v[18 + 4 * t] += w1[j] * vv.z; v[19 + 4 * t] += w1[j] * vv.w;
                }
            }
            // recursive-halving reduce-scatter: 31 SHFLs; lane l ends with
            // fully-reduced logical element l (l<16 -> p0[d=l], else p1[d=l-16]).
#pragma unroll
            for (int off = 16; off >= 1; off >>= 1) {
                const bool hi = (lane & off) != 0;
#pragma unroll
                for (int j = 0; j < 16; j++) {
                    if (j < off) {
                        float send = hi ? v[j] : v[j + off];
                        float keep = hi ? v[j + off] : v[j];
                        v[j] = keep + __shfl_xor_sync(0xffffffffu, send, off);
                    }
                }
            }
            {
                const int d = lane & 15;
                const int p = (lane < 16) ? p0 : p1;
                sQ[p * LDSR + ho + d] = v[0];
            }
        }
    }
    __syncthreads();

    // ---- mh = out_concat @ Wc + bc  (into sK; K matrix is dead) ----
    gemm_tile(sQ, Pn, 128, Wc, sK, bc, sB);

    // ---- score2 = clip*tanh(mh @ nodes^T / sqrt(EMB)) + mask; softmax; store ----
    const float INV_SQRT_EMB = 0.08838834764831843f;  // 1/sqrt(128)
    float* gOut = out + (size_t)b * Pn * Nn;

    for (int pi = warp; pi < Pn / 2; pi += NWARP) {
        const int p0 = 2 * pi, p1 = p0 + 1;
        float m0[4], m1[4];
        int nc[4], nn[4];
#pragma unroll
        for (int j = 0; j < 4; j++) {
            int n = lane + 32 * j;
            nn[j] = n;
            nc[j] = n < Nn ? n : 0;
            m0[j] = n < Nn ? gM[p0 * Nn + n] : -INFINITY;
            m1[j] = n < Nn ? gM[p1 * Nn + n] : -INFINITY;
        }
        float d0[4] = {0, 0, 0, 0}, d1[4] = {0, 0, 0, 0};
        for (int e = 0; e < EMBn; e += 4) {
            float4 a0 = *(const float4*)&sK[p0 * LDSR + e];
            float4 a1 = *(const float4*)&sK[p1 * LDSR + e];
#pragma unroll
            for (int j = 0; j < 4; j++) {
                float4 nv = *(const float4*)&sN[nc[j] * LDSR + e];
                d0[j] += a0.x * nv.x + a0.y * nv.y + a0.z * nv.z + a0.w * nv.w;
                d1[j] += a1.x * nv.x + a1.y * nv.y + a1.z * nv.z + a1.w * nv.w;
            }
        }
        float s0[4], s1[4];
#pragma unroll
        for (int j = 0; j < 4; j++) {
            s0[j] = (nn[j] < Nn) ? tanh10(d0[j] * INV_SQRT_EMB) + m0[j] : -INFINITY;
            s1[j] = (nn[j] < Nn) ? tanh10(d1[j] * INV_SQRT_EMB) + m1[j] : -INFINITY;
        }
        float mx0 = fmaxf(fmaxf(s0[0], s0[1]), fmaxf(s0[2], s0[3]));
        float mx1 = fmaxf(fmaxf(s1[0], s1[1]), fmaxf(s1[2], s1[3]));
#pragma unroll
        for (int off = 16; off; off >>= 1) {
            mx0 = fmaxf(mx0, __shfl_xor_sync(0xffffffffu, mx0, off));
            mx1 = fmaxf(mx1, __shfl_xor_sync(0xffffffffu, mx1, off));
        }
        float w0[4], w1[4], sum0 = 0.f, sum1 = 0.f;
#pragma unroll
        for (int j = 0; j < 4; j++) {
            w0[j] = __expf(s0[j] - mx0); sum0 += w0[j];
            w1[j] = __expf(s1[j] - mx1); sum1 += w1[j];
        }
#pragma unroll
        for (int off = 16; off; off >>= 1) {
            sum0 += __shfl_xor_sync(0xffffffffu, sum0, off);
            sum1 += __shfl_xor_sync(0xffffffffu, sum1, off);
        }
        const float inv0 = 1.f / sum0, inv1 = 1.f / sum1;
#pragma unroll
        for (int j = 0; j < 4; j++) {
            if (nn[j] < Nn) {
                gOut[p0 * Nn + nn[j]] = w0[j] * inv0;
                gOut[p1 * Nn + nn[j]] = w1[j] * inv1;
            }
        }
    }
}

extern "C" void kernel_launch(void* const* d_in, const int* in_sizes, int n_in,
                              void* d_out, int out_size) {
    const float* eln   = (const float*)d_in[0];
    const float* load_ = (const float*)d_in[1];
    const float* time_ = (const float*)d_in[2];
    const float* len_  = (const float*)d_in[3];
    const float* ropen = (const float*)d_in[4];
    const float* mask  = (const float*)d_in[5];
    const float* nodes = (const float*)d_in[6];
    const float* Wq    = (const float*)d_in[7];
    const float* Wk    = (const float*)d_in[8];
    const float* Wv    = (const float*)d_in[9];
    const float* Wc    = (const float*)d_in[10];
    const float* bc    = (const float*)d_in[11];
    float* out = (float*)d_out;

    cudaFuncSetAttribute(vrp_decoder_kernel,
                         cudaFuncAttributeMaxDynamicSharedMemorySize, SMEM_BYTES);
    vrp_decoder_kernel<<<Bn, TPB, SMEM_BYTES>>>(
        eln, load_, time_, len_, ropen, mask, nodes, Wq, Wk, Wv, Wc, bc, out);
}

// round 4
// speedup vs baseline: 1.6170x; 1.2364x over previous
#include <cuda_runtime.h>
#include <cuda_bf16.h>
#include <cstdint>

#define TPB 512
static constexpr int Bn = 1024, Pn = 100, Nn = 101, EMBn = 128;
static constexpr int Hn = 8, DKn = 16;

static constexpr int STB = 40;       // bf16 row stride inside chunk tiles (80B, conflict-free)
static constexpr int CHB = 10240;    // bytes per chunk matrix: 128 rows * 40 bf16 * 2B
// ---- smem byte map ----
static constexpr int SB_H = 0;              // B chunk hi (lo at +CHB)          20480B
static constexpr int SA_H = 20480;          // A chunk hi (lo at +CHB)          20480B
static constexpr int OFF_QF = 40960;        // Q / out_concat / scores [100][132] f32
static constexpr int OFF_KF = 93760;        // K / mh                  [101][132] f32
static constexpr int OFF_VF = 147088;       // V                       [101][132] f32
static constexpr int OFF_EX = 200416;       // extras [100][4] f32
static constexpr int OFF_WQ4 = 202016;      // Wq rows 128..131  [4][128] f32
static constexpr int OFF_BC = 204064;       // bc [128] f32
static constexpr int SMEM_TOTAL = 204576;
static constexpr int LDSR = 132;            // f32 row stride

// ---------------- prep: weights -> chunk-blocked bf16 hi/lo, B^T layout ----
// g_wt[w]: 4 chunks; chunk c: hi elems [c*10240 .. +5119], lo at +5120.
// elem index within chunk: n*40 + (k&31);  B^T[n][k] = W[k][n].
__device__ __nv_bfloat16 g_wt[4][40960];
__device__ float g_wq4[512];

__global__ void prep_weights(const float* __restrict__ Wq, const float* __restrict__ Wk,
                             const float* __restrict__ Wv, const float* __restrict__ Wc)
{
    const int w = blockIdx.x;
    const float* W = (w == 0) ? Wq : (w == 1) ? Wk : (w == 2) ? Wv : Wc;
    for (int idx = threadIdx.x; idx < 128 * 128; idx += blockDim.x) {
        int n = idx >> 7, k = idx & 127;
        float x = W[k * 128 + n];
        __nv_bfloat16 h = __float2bfloat16(x);
        __nv_bfloat16 l = __float2bfloat16(x - __bfloat162float(h));
        int o = (k >> 5) * 10240 + n * STB + (k & 31);
        g_wt[w][o] = h;
        g_wt[w][o + 5120] = l;
    }
    if (w == 0) {
        for (int i = threadIdx.x; i < 512; i += blockDim.x)
            g_wq4[i] = Wq[128 * 128 + i];   // [j][n], j=0..3
    }
}

// ---------------- device helpers ----------------
__device__ __forceinline__ uint32_t smem_u32(const void* p) {
    uint32_t a;
    asm("{ .reg .u64 t; cvta.to.shared.u64 t, %1; cvt.u32.u64 %0, t; }" : "=r"(a) : "l"(p));
    return a;
}
__device__ __forceinline__ float tanh10(float x) {
    x = fminf(fmaxf(x, -20.f), 20.f);
    float t = __expf(2.f * x);
    return 10.f * (t - 1.f) / (t + 1.f);
}

#define LDSM4(R0, R1, R2, R3, ADDR) \
    asm volatile("ldmatrix.sync.aligned.m8n8.x4.shared.b16 {%0,%1,%2,%3}, [%4];" \
        : "=r"(R0), "=r"(R1), "=r"(R2), "=r"(R3) : "r"(ADDR))

#define MMA16816(C, A, B0, B1) \
    asm volatile("mma.sync.aligned.m16n8k16.row.col.f32.bf16.bf16.f32 " \
        "{%0,%1,%2,%3}, {%4,%5,%6,%7}, {%8,%9}, {%0,%1,%2,%3};" \
        : "+f"((C)[0]), "+f"((C)[1]), "+f"((C)[2]), "+f"((C)[3]) \
        : "r"((A)[0]), "r"((A)[1]), "r"((A)[2]), "r"((A)[3]), "r"(B0), "r"(B1))

// build one 128x32 hi/lo bf16 chunk (dst = hi base, lo at dst+5120 elems)
// from an f32 row-major source; rows >= nrows are zeroed; optional bias[k].
__device__ __forceinline__ void build_half(
    __nv_bfloat16* __restrict__ dst, const float* __restrict__ src,
    int ld, int nrows, int k0, const float* __restrict__ biasK)
{
    for (int i = threadIdx.x; i < 1024; i += TPB) {
        int r = i >> 3, q = (i & 7) << 2;
        float4 v = make_float4(0.f, 0.f, 0.f, 0.f);
        if (r < nrows) v = *(const float4*)&src[(size_t)r * ld + k0 + q];
        if (biasK) {
            v.x += biasK[k0 + q];     v.y += biasK[k0 + q + 1];
            v.z += biasK[k0 + q + 2]; v.w += biasK[k0 + q + 3];
        }
        __nv_bfloat162 h01 = __floats2bfloat162_rn(v.x, v.y);
        __nv_bfloat162 h23 = __floats2bfloat162_rn(v.z, v.w);
        __nv_bfloat162 l01 = __floats2bfloat162_rn(v.x - __bfloat162float(h01.x),
                                                   v.y - __bfloat162float(h01.y));
        __nv_bfloat162 l23 = __floats2bfloat162_rn(v.z - __bfloat162float(h23.x),
                                                   v.w - __bfloat162float(h23.y));
        int o = r * STB + q;
        *(__nv_bfloat162*)(dst + o)            = h01;
        *(__nv_bfloat162*)(dst + o + 2)        = h23;
        *(__nv_bfloat162*)(dst + 5120 + o)     = l01;
        *(__nv_bfloat162*)(dst + 5120 + o + 2) = l23;
    }
}

// C[128pad,128] = A[.,128] @ B[128,128] via mma.sync, hi/lo split (3 products).
// A: f32 row-major (gmem or smem). B: wsel>=0 -> prepped weight; else f32 [Bnrows][128]
// (B^T row-major). C: f32 smem, stride 132, rows < Cnrows stored.
__device__ __noinline__ void gemm128(
    unsigned char* smem8, uint32_t sb,
    const float* __restrict__ Asrc, int Ald, int Anrows, const float* __restrict__ biasK,
    int wsel, const float* __restrict__ Bf32, int Bnrows,
    float* __restrict__ Cdst, int Cnrows)
{
    const int tid = threadIdx.x, w = tid >> 5, lane = tid & 31;
    const int wm = w & 3, wn = w >> 2;

    float acc[2][4][4];
#pragma unroll
    for (int m = 0; m < 2; m++)
#pragma unroll
        for (int n = 0; n < 4; n++)
#pragma unroll
            for (int j = 0; j < 4; j++) acc[m][n][j] = 0.f;

    for (int c = 0; c < 4; c++) {
        __syncthreads();   // protect operand buffers from previous users
        const int k0 = c * 32;
        build_half((__nv_bfloat16*)(smem8 + SA_H), Asrc, Ald, Anrows, k0, biasK);
        if (wsel >= 0) {
            const uint4* src = (const uint4*)&g_wt[wsel][c * 10240];
            uint4* dst = (uint4*)(smem8 + SB_H);
            for (int i = tid; i < 1280; i += TPB) dst[i] = src[i];
        } else {
            build_half((__nv_bfloat16*)(smem8 + SB_H), Bf32, 128, Bnrows, k0, nullptr);
        }
        __syncthreads();

#pragma unroll
        for (int pass = 0; pass < 3; pass++) {
            const uint32_t Aoff = SA_H + (pass == 2 ? CHB : 0);
            const uint32_t Boff = SB_H + (pass == 1 ? CHB : 0);
#pragma unroll
            for (int ks = 0; ks < 2; ks++) {
                const int kb = ks * 16;
                uint32_t a[2][4];
#pragma unroll
                for (int m = 0; m < 2; m++) {
                    uint32_t addr = sb + Aoff +
                        (uint32_t)(((wm * 32 + m * 16 + (lane & 15)) * STB
                                    + kb + ((lane >> 4) << 3)) << 1);
                    LDSM4(a[m][0], a[m][1], a[m][2], a[m][3], addr);
                }
                uint32_t bfr[4][2];
#pragma unroll
                for (int t = 0; t < 2; t++) {
                    const int n0 = wn * 32 + t * 16;
                    uint32_t addr = sb + Boff +
                        (uint32_t)(((n0 + ((lane & 16) ? 8 : 0) + (lane & 7)) * STB
                                    + kb + ((lane & 8) ? 8 : 0)) << 1);
                    uint32_t r0, r1, r2, r3;
                    LDSM4(r0, r1, r2, r3, addr);
                    bfr[2 * t][0] = r0;     bfr[2 * t][1] = r1;
                    bfr[2 * t + 1][0] = r2; bfr[2 * t + 1][1] = r3;
                }
#pragma unroll
                for (int m = 0; m < 2; m++)
#pragma unroll
                    for (int n = 0; n < 4; n++)
                        MMA16816(acc[m][n], a[m], bfr[n][0], bfr[n][1]);
            }
        }
    }
    __syncthreads();
#pragma unroll
    for (int m = 0; m < 2; m++) {
#pragma unroll
        for (int n = 0; n < 4; n++) {
            const int row = wm * 32 + m * 16 + (lane >> 2);
            const int col = wn * 32 + n * 8 + ((lane & 3) << 1);
            if (row < Cnrows)
                *(float2*)&Cdst[row * LDSR + col] = make_float2(acc[m][n][0], acc[m][n][1]);
            if (row + 8 < Cnrows)
                *(float2*)&Cdst[(row + 8) * LDSR + col] = make_float2(acc[m][n][2], acc[m][n][3]);
        }
    }
    __syncthreads();
}

extern __shared__ __align__(16) unsigned char smem8[];

__global__ __launch_bounds__(TPB, 1)
void vrp_decoder_kernel(
    const float* __restrict__ eln,   const float* __restrict__ load_,
    const float* __restrict__ time_, const float* __restrict__ len_,
    const float* __restrict__ ropen, const float* __restrict__ mask,
    const float* __restrict__ nodes, const float* __restrict__ bc,
    float* __restrict__ out)
{
    const int b = blockIdx.x;
    const int tid = threadIdx.x;
    const int wid = tid >> 5, lane = tid & 31;
    const uint32_t sb = smem_u32(smem8);

    float* sQf  = (float*)(smem8 + OFF_QF);
    float* sKf  = (float*)(smem8 + OFF_KF);
    float* sVf  = (float*)(smem8 + OFF_VF);
    float* sEx  = (float*)(smem8 + OFF_EX);
    float* sWq4 = (float*)(smem8 + OFF_WQ4);
    float* sBc  = (float*)(smem8 + OFF_BC);

    // ---- stage aux ----
    for (int i = tid; i < 512; i += TPB) sWq4[i] = g_wq4[i];
    for (int i = tid; i < 128; i += TPB) sBc[i] = bc[i];
    for (int r = tid; r < Pn; r += TPB) {
        sEx[r * 4 + 0] = load_[b * Pn + r];
        sEx[r * 4 + 1] = time_[b * Pn + r];
        sEx[r * 4 + 2] = len_[b * Pn + r];
        sEx[r * 4 + 3] = ropen[b * Pn + r];
    }

    const float* gE = eln + (size_t)b * Pn * EMBn;
    const float* gN = nodes + (size_t)b * Nn * EMBn;

    // ---- Q = eln @ Wq[0:128]  (internal syncs order the aux stores too) ----
    gemm128(smem8, sb, gE, EMBn, Pn, nullptr, 0, nullptr, 0, sQf, Pn);
    // add the 4-extra-feature correction: Q[r][c] += sum_j ex[r][j]*Wq4[j][c]
    for (int i = tid; i < Pn * 32; i += TPB) {
        int r = i >> 5, cq = (i & 31) << 2;
        float4 qv = *(float4*)&sQf[r * LDSR + cq];
        float e0 = sEx[r * 4 + 0], e1 = sEx[r * 4 + 1];
        float e2 = sEx[r * 4 + 2], e3 = sEx[r * 4 + 3];
        qv.x += e0 * sWq4[cq + 0] + e1 * sWq4[128 + cq + 0] + e2 * sWq4[256 + cq + 0] + e3 * sWq4[384 + cq + 0];
        qv.y += e0 * sWq4[cq + 1] + e1 * sWq4[128 + cq + 1] + e2 * sWq4[256 + cq + 1] + e3 * sWq4[384 + cq + 1];
        qv.z += e0 * sWq4[cq + 2] + e1 * sWq4[128 + cq + 2] + e2 * sWq4[256 + cq + 2] + e3 * sWq4[384 + cq + 2];
        qv.w += e0 * sWq4[cq + 3] + e1 * sWq4[128 + cq + 3] + e2 * sWq4[256 + cq + 3] + e3 * sWq4[384 + cq + 3];
        *(float4*)&sQf[r * LDSR + cq] = qv;
    }
    // ---- K, V = nodes @ Wk / Wv ----
    gemm128(smem8, sb, gN, EMBn, Nn, nullptr, 1, nullptr, 0, sKf, Nn);
    gemm128(smem8, sb, gN, EMBn, Nn, nullptr, 2, nullptr, 0, sVf, Nn);

    // ---- attention: warp per row-pair; out written IN PLACE over Q ----
    const float* gM = mask + (size_t)b * Pn * Nn;
    const int NWARP = TPB / 32;
    for (int pi = wid; pi < Pn / 2; pi += NWARP) {
        const int p0 = 2 * pi, p1 = p0 + 1;
        float m0[4], m1[4];
        int nc[4];
#pragma unroll
        for (int j = 0; j < 4; j++) {
            int n = lane + 32 * j;
            nc[j] = n < Nn ? n : 0;
            m0[j] = n < Nn ? gM[p0 * Nn + n] : -INFINITY;
            m1[j] = n < Nn ? gM[p1 * Nn + n] : -INFINITY;
        }
        for (int h = 0; h < Hn; h++) {
            const int ho = h * DKn;
            float4 q0[4], q1[4];
#pragma unroll
            for (int t = 0; t < 4; t++) {
                q0[t] = *(const float4*)&sQf[p0 * LDSR + ho + 4 * t];
                q1[t] = *(const float4*)&sQf[p1 * LDSR + ho + 4 * t];
            }
            float s0[4], s1[4];
#pragma unroll
            for (int j = 0; j < 4; j++) {
                const float* kr = &sKf[nc[j] * LDSR + ho];
                float a0 = 0.f, a1 = 0.f;
#pragma unroll
                for (int t = 0; t < 4; t++) {
                    float4 kv = *(const float4*)&kr[4 * t];
                    a0 += q0[t].x * kv.x + q0[t].y * kv.y + q0[t].z * kv.z + q0[t].w * kv.w;
                    a1 += q1[t].x * kv.x + q1[t].y * kv.y + q1[t].z * kv.z + q1[t].w * kv.w;
                }
                s0[j] = a0 * 0.25f + m0[j];
                s1[j] = a1 * 0.25f + m1[j];
            }
            float mx0 = fmaxf(fmaxf(s0[0], s0[1]), fmaxf(s0[2], s0[3]));
            float mx1 = fmaxf(fmaxf(s1[0], s1[1]), fmaxf(s1[2], s1[3]));
#pragma unroll
            for (int off = 16; off; off >>= 1) {
                mx0 = fmaxf(mx0, __shfl_xor_sync(0xffffffffu, mx0, off));
                mx1 = fmaxf(mx1, __shfl_xor_sync(0xffffffffu, mx1, off));
            }
            float w0[4], w1[4], sum0 = 0.f, sum1 = 0.f;
#pragma unroll
            for (int j = 0; j < 4; j++) {
                w0[j] = __expf(s0[j] - mx0); sum0 += w0[j];
                w1[j] = __expf(s1[j] - mx1); sum1 += w1[j];
            }
#pragma unroll
            for (int off = 16; off; off >>= 1) {
                sum0 += __shfl_xor_sync(0xffffffffu, sum0, off);
                sum1 += __shfl_xor_sync(0xffffffffu, sum1, off);
            }
            const float inv0 = 1.f / sum0, inv1 = 1.f / sum1;
#pragma unroll
            for (int j = 0; j < 4; j++) { w0[j] *= inv0; w1[j] *= inv1; }

            float v[32];
#pragma unroll
            for (int d = 0; d < 32; d++) v[d] = 0.f;
#pragma unroll
            for (int j = 0; j < 4; j++) {
                const float* vr = &sVf[nc[j] * LDSR + ho];
#pragma unroll
                for (int t = 0; t < 4; t++) {
                    float4 vv = *(const float4*)&vr[4 * t];
                    v[4 * t + 0]  += w0[j] * vv.x; v[4 * t + 1]  += w0[j] * vv.y;
                    v[4 * t + 2]  += w0[j] * vv.z; v[4 * t + 3]  += w0[j] * vv.w;
                    v[16 + 4 * t] += w1[j] * vv.x; v[17 + 4 * t] += w1[j] * vv.y;
                    v[18 + 4 * t] += w1[j] * vv.z; v[19 + 4 * t] += w1[j] * vv.w;
                }
            }
#pragma unroll
            for (int off = 16; off >= 1; off >>= 1) {
                const bool hi = (lane & off) != 0;
#pragma unroll
                for (int j = 0; j < 16; j++) {
                    if (j < off) {
                        float send = hi ? v[j] : v[j + off];
                        float keep = hi ? v[j + off] : v[j];
                        v[j] = keep + __shfl_xor_sync(0xffffffffu, send, off);
                    }
                }
            }
            {
                const int d = lane & 15;
                const int p = (lane < 16) ? p0 : p1;
                sQf[p * LDSR + ho + d] = v[0];   // in-place over Q
            }
        }
    }

    // ---- mh = out_concat @ Wc (bias folded into next A-build); C -> sKf ----
    gemm128(smem8, sb, sQf, LDSR, Pn, nullptr, 3, nullptr, 0, sKf, Pn);
    // ---- score2 = (mh + bc) @ nodes^T; C -> sQf ----
    gemm128(smem8, sb, sKf, LDSR, Pn, sBc, -1, gN, Nn, sQf, Pn);

    // ---- final: clip*tanh(score2/sqrt(128)) + mask; softmax; store ----
    const float INV_SQRT_EMB = 0.08838834764831843f;
    float* gOut = out + (size_t)b * Pn * Nn;
    for (int pi = wid; pi < Pn / 2; pi += NWARP) {
        const int p0 = 2 * pi, p1 = p0 + 1;
        float s0[4], s1[4];
        int nn[4];
#pragma unroll
        for (int j = 0; j < 4; j++) {
            int n = lane + 32 * j;
            nn[j] = n;
            if (n < Nn) {
                s0[j] = tanh10(sQf[p0 * LDSR + n] * INV_SQRT_EMB) + gM[p0 * Nn + n];
                s1[j] = tanh10(sQf[p1 * LDSR + n] * INV_SQRT_EMB) + gM[p1 * Nn + n];
            } else { s0[j] = -INFINITY; s1[j] = -INFINITY; }
        }
        float mx0 = fmaxf(fmaxf(s0[0], s0[1]), fmaxf(s0[2], s0[3]));
        float mx1 = fmaxf(fmaxf(s1[0], s1[1]), fmaxf(s1[2], s1[3]));
#pragma unroll
        for (int off = 16; off; off >>= 1) {
            mx0 = fmaxf(mx0, __shfl_xor_sync(0xffffffffu, mx0, off));
            mx1 = fmaxf(mx1, __shfl_xor_sync(0xffffffffu, mx1, off));
        }
        float w0[4], w1[4], sum0 = 0.f, sum1 = 0.f;
#pragma unroll
        for (int j = 0; j < 4; j++) {
            w0[j] = __expf(s0[j] - mx0); sum0 += w0[j];
            w1[j] = __expf(s1[j] - mx1); sum1 += w1[j];
        }
#pragma unroll
        for (int off = 16; off; off >>= 1) {
            sum0 += __shfl_xor_sync(0xffffffffu, sum0, off);
            sum1 += __shfl_xor_sync(0xffffffffu, sum1, off);
        }
        const float inv0 = 1.f / sum0, inv1 = 1.f / sum1;
#pragma unroll
        for (int j = 0; j < 4; j++) {
            if (nn[j] < Nn) {
                gOut[p0 * Nn + nn[j]] = w0[j] * inv0;
                gOut[p1 * Nn + nn[j]] = w1[j] * inv1;
            }
        }
    }
}

extern "C" void kernel_launch(void* const* d_in, const int* in_sizes, int n_in,
                              void* d_out, int out_size) {
    const float* eln   = (const float*)d_in[0];
    const float* load_ = (const float*)d_in[1];
    const float* time_ = (const float*)d_in[2];
    const float* len_  = (const float*)d_in[3];
    const float* ropen = (const float*)d_in[4];
    const float* mask  = (const float*)d_in[5];
    const float* nodes = (const float*)d_in[6];
    const float* Wq    = (const float*)d_in[7];
    const float* Wk    = (const float*)d_in[8];
    const float* Wv    = (const float*)d_in[9];
    const float* Wc    = (const float*)d_in[10];
    const float* bc    = (const float*)d_in[11];
    float* out = (float*)d_out;

    prep_weights<<<4, 256>>>(Wq, Wk, Wv, Wc);
    cudaFuncSetAttribute(vrp_decoder_kernel,
                         cudaFuncAttributeMaxDynamicSharedMemorySize, SMEM_TOTAL);
    vrp_decoder_kernel<<<Bn, TPB, SMEM_TOTAL>>>(
        eln, load_, time_, len_, ropen, mask, nodes, bc, out);
}

// round 5
// speedup vs baseline: 1.6911x; 1.0458x over previous
#include <cuda_runtime.h>
#include <cuda_bf16.h>
#include <cstdint>

#define TPB 512
static constexpr int Bn = 1024, Pn = 100, Nn = 101, EMBn = 128;
static constexpr int Hn = 8, DKn = 16;

static constexpr int STB = 40;       // bf16 row stride inside chunk tiles (80B, conflict-free)
static constexpr int CHB = 10240;    // bytes per chunk matrix: 128 rows * 40 bf16 * 2B
// ---- smem byte map ----
static constexpr int SB_H = 0;              // B chunk hi (lo at +CHB)          20480B
static constexpr int SA_H = 20480;          // A chunk hi (lo at +CHB)          20480B
static constexpr int OFF_QF = 40960;        // Q / out_concat / scores [100][132] f32
static constexpr int OFF_KF = 93760;        // K / mh                  [101][132] f32
static constexpr int OFF_VF = 147088;       // V                       [101][132] f32
static constexpr int OFF_EX = 200416;       // extras [100][4] f32
static constexpr int OFF_WQ4 = 202016;      // Wq rows 128..131  [4][128] f32
static constexpr int OFF_BC = 204064;       // bc [128] f32
static constexpr int SMEM_TOTAL = 204576;
static constexpr int LDSR = 132;            // f32 row stride

// ---------------- prep: weights -> chunk-blocked bf16 hi/lo, B^T layout ----
__device__ __nv_bfloat16 g_wt[4][40960];
__device__ float g_wq4[512];

__global__ void prep_weights(const float* __restrict__ Wq, const float* __restrict__ Wk,
                             const float* __restrict__ Wv, const float* __restrict__ Wc)
{
    const int w = blockIdx.x;
    const float* W = (w == 0) ? Wq : (w == 1) ? Wk : (w == 2) ? Wv : Wc;
    for (int idx = threadIdx.x; idx < 128 * 128; idx += blockDim.x) {
        int n = idx >> 7, k = idx & 127;
        float x = W[k * 128 + n];
        __nv_bfloat16 h = __float2bfloat16(x);
        __nv_bfloat16 l = __float2bfloat16(x - __bfloat162float(h));
        int o = (k >> 5) * 10240 + n * STB + (k & 31);
        g_wt[w][o] = h;
        g_wt[w][o + 5120] = l;
    }
    if (w == 0) {
        for (int i = threadIdx.x; i < 512; i += blockDim.x)
            g_wq4[i] = Wq[128 * 128 + i];
    }
}

// ---------------- device helpers ----------------
__device__ __forceinline__ uint32_t smem_u32(const void* p) {
    uint32_t a;
    asm("{ .reg .u64 t; cvta.to.shared.u64 t, %1; cvt.u32.u64 %0, t; }" : "=r"(a) : "l"(p));
    return a;
}
__device__ __forceinline__ float tanh10(float x) {
    x = fminf(fmaxf(x, -20.f), 20.f);
    float t = __expf(2.f * x);
    return 10.f * (t - 1.f) / (t + 1.f);
}

#define LDSM4(R0, R1, R2, R3, ADDR) \
    asm volatile("ldmatrix.sync.aligned.m8n8.x4.shared.b16 {%0,%1,%2,%3}, [%4];" \
        : "=r"(R0), "=r"(R1), "=r"(R2), "=r"(R3) : "r"(ADDR))

#define MMA16816(C, A, B0, B1) \
    asm volatile("mma.sync.aligned.m16n8k16.row.col.f32.bf16.bf16.f32 " \
        "{%0,%1,%2,%3}, {%4,%5,%6,%7}, {%8,%9}, {%0,%1,%2,%3};" \
        : "+f"((C)[0]), "+f"((C)[1]), "+f"((C)[2]), "+f"((C)[3]) \
        : "r"((A)[0]), "r"((A)[1]), "r"((A)[2]), "r"((A)[3]), "r"(B0), "r"(B1))

// 32-value recursive-halving reduce-scatter at compile-time base offset.
template<int BASE>
__device__ __forceinline__ void reduce32(float* v, int lane) {
#pragma unroll
    for (int off = 16; off >= 1; off >>= 1) {
        const bool hi = (lane & off) != 0;
#pragma unroll
        for (int j = 0; j < 16; j++) {
            if (j < off) {
                float send = hi ? v[BASE + j] : v[BASE + j + off];
                float keep = hi ? v[BASE + j + off] : v[BASE + j];
                v[BASE + j] = keep + __shfl_xor_sync(0xffffffffu, send, off);
            }
        }
    }
}

// build one 128x32 hi/lo bf16 chunk from f32 row-major source
__device__ __forceinline__ void build_half(
    __nv_bfloat16* __restrict__ dst, const float* __restrict__ src,
    int ld, int nrows, int k0, const float* __restrict__ biasK)
{
    for (int i = threadIdx.x; i < 1024; i += TPB) {
        int r = i >> 3, q = (i & 7) << 2;
        float4 v = make_float4(0.f, 0.f, 0.f, 0.f);
        if (r < nrows) v = *(const float4*)&src[(size_t)r * ld + k0 + q];
        if (biasK) {
            v.x += biasK[k0 + q];     v.y += biasK[k0 + q + 1];
            v.z += biasK[k0 + q + 2]; v.w += biasK[k0 + q + 3];
        }
        __nv_bfloat162 h01 = __floats2bfloat162_rn(v.x, v.y);
        __nv_bfloat162 h23 = __floats2bfloat162_rn(v.z, v.w);
        __nv_bfloat162 l01 = __floats2bfloat162_rn(v.x - __bfloat162float(h01.x),
                                                   v.y - __bfloat162float(h01.y));
        __nv_bfloat162 l23 = __floats2bfloat162_rn(v.z - __bfloat162float(h23.x),
                                                   v.w - __bfloat162float(h23.y));
        int o = r * STB + q;
        *(__nv_bfloat162*)(dst + o)            = h01;
        *(__nv_bfloat162*)(dst + o + 2)        = h23;
        *(__nv_bfloat162*)(dst + 5120 + o)     = l01;
        *(__nv_bfloat162*)(dst + 5120 + o + 2) = l23;
    }
}

// C = A @ B via mma.sync, hi/lo split (3 products). See R4 notes.
__device__ __noinline__ void gemm128(
    unsigned char* smem8, uint32_t sb,
    const float* __restrict__ Asrc, int Ald, int Anrows, const float* __restrict__ biasK,
    int wsel, const float* __restrict__ Bf32, int Bnrows,
    float* __restrict__ Cdst, int Cnrows)
{
    const int tid = threadIdx.x, w = tid >> 5, lane = tid & 31;
    const int wm = w & 3, wn = w >> 2;

    float acc[2][4][4];
#pragma unroll
    for (int m = 0; m < 2; m++)
#pragma unroll
        for (int n = 0; n < 4; n++)
#pragma unroll
            for (int j = 0; j < 4; j++) acc[m][n][j] = 0.f;

    for (int c = 0; c < 4; c++) {
        __syncthreads();
        const int k0 = c * 32;
        build_half((__nv_bfloat16*)(smem8 + SA_H), Asrc, Ald, Anrows, k0, biasK);
        if (wsel >= 0) {
            const uint4* src = (const uint4*)&g_wt[wsel][c * 10240];
            uint4* dst = (uint4*)(smem8 + SB_H);
            for (int i = tid; i < 1280; i += TPB) dst[i] = src[i];
        } else {
            build_half((__nv_bfloat16*)(smem8 + SB_H), Bf32, 128, Bnrows, k0, nullptr);
        }
        __syncthreads();

#pragma unroll
        for (int pass = 0; pass < 3; pass++) {
            const uint32_t Aoff = SA_H + (pass == 2 ? CHB : 0);
            const uint32_t Boff = SB_H + (pass == 1 ? CHB : 0);
#pragma unroll
            for (int ks = 0; ks < 2; ks++) {
                const int kb = ks * 16;
                uint32_t a[2][4];
#pragma unroll
                for (int m = 0; m < 2; m++) {
                    uint32_t addr = sb + Aoff +
                        (uint32_t)(((wm * 32 + m * 16 + (lane & 15)) * STB
                                    + kb + ((lane >> 4) << 3)) << 1);
                    LDSM4(a[m][0], a[m][1], a[m][2], a[m][3], addr);
                }
                uint32_t bfr[4][2];
#pragma unroll
                for (int t = 0; t < 2; t++) {
                    const int n0 = wn * 32 + t * 16;
                    uint32_t addr = sb + Boff +
                        (uint32_t)(((n0 + ((lane & 16) ? 8 : 0) + (lane & 7)) * STB
                                    + kb + ((lane & 8) ? 8 : 0)) << 1);
                    uint32_t r0, r1, r2, r3;
                    LDSM4(r0, r1, r2, r3, addr);
                    bfr[2 * t][0] = r0;     bfr[2 * t][1] = r1;
                    bfr[2 * t + 1][0] = r2; bfr[2 * t + 1][1] = r3;
                }
#pragma unroll
                for (int m = 0; m < 2; m++)
#pragma unroll
                    for (int n = 0; n < 4; n++)
                        MMA16816(acc[m][n], a[m], bfr[n][0], bfr[n][1]);
            }
        }
    }
    __syncthreads();
#pragma unroll
    for (int m = 0; m < 2; m++) {
#pragma unroll
        for (int n = 0; n < 4; n++) {
            const int row = wm * 32 + m * 16 + (lane >> 2);
            const int col = wn * 32 + n * 8 + ((lane & 3) << 1);
            if (row < Cnrows)
                *(float2*)&Cdst[row * LDSR + col] = make_float2(acc[m][n][0], acc[m][n][1]);
            if (row + 8 < Cnrows)
                *(float2*)&Cdst[(row + 8) * LDSR + col] = make_float2(acc[m][n][2], acc[m][n][3]);
        }
    }
    __syncthreads();
}

extern __shared__ __align__(16) unsigned char smem8[];

__global__ __launch_bounds__(TPB, 1)
void vrp_decoder_kernel(
    const float* __restrict__ eln,   const float* __restrict__ load_,
    const float* __restrict__ time_, const float* __restrict__ len_,
    const float* __restrict__ ropen, const float* __restrict__ mask,
    const float* __restrict__ nodes, const float* __restrict__ bc,
    float* __restrict__ out)
{
    const int b = blockIdx.x;
    const int tid = threadIdx.x;
    const int wid = tid >> 5, lane = tid & 31;
    const uint32_t sb = smem_u32(smem8);

    float* sQf  = (float*)(smem8 + OFF_QF);
    float* sKf  = (float*)(smem8 + OFF_KF);
    float* sVf  = (float*)(smem8 + OFF_VF);
    float* sEx  = (float*)(smem8 + OFF_EX);
    float* sWq4 = (float*)(smem8 + OFF_WQ4);
    float* sBc  = (float*)(smem8 + OFF_BC);

    // ---- stage aux ----
    for (int i = tid; i < 512; i += TPB) sWq4[i] = g_wq4[i];
    for (int i = tid; i < 128; i += TPB) sBc[i] = bc[i];
    for (int r = tid; r < Pn; r += TPB) {
        sEx[r * 4 + 0] = load_[b * Pn + r];
        sEx[r * 4 + 1] = time_[b * Pn + r];
        sEx[r * 4 + 2] = len_[b * Pn + r];
        sEx[r * 4 + 3] = ropen[b * Pn + r];
    }

    const float* gE = eln + (size_t)b * Pn * EMBn;
    const float* gN = nodes + (size_t)b * Nn * EMBn;

    // ---- Q = eln @ Wq[0:128] ----
    gemm128(smem8, sb, gE, EMBn, Pn, nullptr, 0, nullptr, 0, sQf, Pn);
    // 4-extra-feature correction
    for (int i = tid; i < Pn * 32; i += TPB) {
        int r = i >> 5, cq = (i & 31) << 2;
        float4 qv = *(float4*)&sQf[r * LDSR + cq];
        float e0 = sEx[r * 4 + 0], e1 = sEx[r * 4 + 1];
        float e2 = sEx[r * 4 + 2], e3 = sEx[r * 4 + 3];
        qv.x += e0 * sWq4[cq + 0] + e1 * sWq4[128 + cq + 0] + e2 * sWq4[256 + cq + 0] + e3 * sWq4[384 + cq + 0];
        qv.y += e0 * sWq4[cq + 1] + e1 * sWq4[128 + cq + 1] + e2 * sWq4[256 + cq + 1] + e3 * sWq4[384 + cq + 1];
        qv.z += e0 * sWq4[cq + 2] + e1 * sWq4[128 + cq + 2] + e2 * sWq4[256 + cq + 2] + e3 * sWq4[384 + cq + 2];
        qv.w += e0 * sWq4[cq + 3] + e1 * sWq4[128 + cq + 3] + e2 * sWq4[256 + cq + 3] + e3 * sWq4[384 + cq + 3];
        *(float4*)&sQf[r * LDSR + cq] = qv;
    }
    // ---- K, V = nodes @ Wk / Wv ----
    gemm128(smem8, sb, gN, EMBn, Nn, nullptr, 1, nullptr, 0, sKf, Nn);
    gemm128(smem8, sb, gN, EMBn, Nn, nullptr, 2, nullptr, 0, sVf, Nn);

    // ---- attention: warp per 4-row group (25 groups); out IN PLACE over Q ----
    const float* gM = mask + (size_t)b * Pn * Nn;
    const int NWARP = TPB / 32;
    for (int g = wid; g < 25; g += NWARP) {
        const int pb = g * 4;
        for (int h = 0; h < Hn; h++) {
            const int ho = h * DKn;
            // scores: s[r][j] for rows pb..pb+3, n = lane + 32j
            float s[4][4];
#pragma unroll
            for (int j = 0; j < 4; j++) {
                const int n = lane + 32 * j;
                const int ncj = n < Nn ? n : 0;
                const float* kr = &sKf[ncj * LDSR + ho];
                float4 k0 = *(const float4*)&kr[0],  k1 = *(const float4*)&kr[4];
                float4 k2 = *(const float4*)&kr[8],  k3 = *(const float4*)&kr[12];
#pragma unroll
                for (int r = 0; r < 4; r++) {
                    const float* qr = &sQf[(pb + r) * LDSR + ho];
                    float4 q0 = *(const float4*)&qr[0],  q1 = *(const float4*)&qr[4];
                    float4 q2 = *(const float4*)&qr[8],  q3 = *(const float4*)&qr[12];
                    float dot = q0.x * k0.x + q0.y * k0.y + q0.z * k0.z + q0.w * k0.w
                              + q1.x * k1.x + q1.y * k1.y + q1.z * k1.z + q1.w * k1.w
                              + q2.x * k2.x + q2.y * k2.y + q2.z * k2.z + q2.w * k2.w
                              + q3.x * k3.x + q3.y * k3.y + q3.z * k3.z + q3.w * k3.w;
                    s[r][j] = (n < Nn) ? (dot * 0.25f + gM[(pb + r) * Nn + n]) : -INFINITY;
                }
            }
            // per-row softmax -> weights in place
#pragma unroll
            for (int r = 0; r < 4; r++) {
                float mx = fmaxf(fmaxf(s[r][0], s[r][1]), fmaxf(s[r][2], s[r][3]));
#pragma unroll
                for (int off = 16; off; off >>= 1)
                    mx = fmaxf(mx, __shfl_xor_sync(0xffffffffu, mx, off));
                float sum = 0.f;
#pragma unroll
                for (int j = 0; j < 4; j++) { s[r][j] = __expf(s[r][j] - mx); sum += s[r][j]; }
#pragma unroll
                for (int off = 16; off; off >>= 1)
                    sum += __shfl_xor_sync(0xffffffffu, sum, off);
                const float inv = 1.f / sum;
#pragma unroll
                for (int j = 0; j < 4; j++) s[r][j] *= inv;
            }
            // PV partials: v[r*16 + d]
            float v[64];
#pragma unroll
            for (int d = 0; d < 64; d++) v[d] = 0.f;
#pragma unroll
            for (int j = 0; j < 4; j++) {
                const int n = lane + 32 * j;
                const int ncj = n < Nn ? n : 0;
                const float* vr = &sVf[ncj * LDSR + ho];
                float4 v0 = *(const float4*)&vr[0],  v1 = *(const float4*)&vr[4];
                float4 v2 = *(const float4*)&vr[8],  v3 = *(const float4*)&vr[12];
#pragma unroll
                for (int r = 0; r < 4; r++) {
                    const float wr = s[r][j];
                    v[r * 16 + 0]  += wr * v0.x; v[r * 16 + 1]  += wr * v0.y;
                    v[r * 16 + 2]  += wr * v0.z; v[r * 16 + 3]  += wr * v0.w;
                    v[r * 16 + 4]  += wr * v1.x; v[r * 16 + 5]  += wr * v1.y;
                    v[r * 16 + 6]  += wr * v1.z; v[r * 16 + 7]  += wr * v1.w;
                    v[r * 16 + 8]  += wr * v2.x; v[r * 16 + 9]  += wr * v2.y;
                    v[r * 16 + 10] += wr * v2.z; v[r * 16 + 11] += wr * v2.w;
                    v[r * 16 + 12] += wr * v3.x; v[r * 16 + 13] += wr * v3.y;
                    v[r * 16 + 14] += wr * v3.z; v[r * 16 + 15] += wr * v3.w;
                }
            }
            // two 32-value reduce-scatters: block0 rows pb..pb+1, block1 rows pb+2..pb+3
            reduce32<0>(v, lane);
            reduce32<32>(v, lane);
            {
                const int d = lane & 15;
                const int r = (lane < 16) ? 0 : 1;
                sQf[(pb + r) * LDSR + ho + d]     = v[0];
                sQf[(pb + 2 + r) * LDSR + ho + d] = v[32];
            }
        }
    }

    // ---- mh = out_concat @ Wc; C -> sKf ----
    gemm128(smem8, sb, sQf, LDSR, Pn, nullptr, 3, nullptr, 0, sKf, Pn);
    // ---- score2 = (mh + bc) @ nodes^T; C -> sQf ----
    gemm128(smem8, sb, sKf, LDSR, Pn, sBc, -1, gN, Nn, sQf, Pn);

    // ---- final: clip*tanh(score2/sqrt(128)) + mask; softmax; store ----
    const float INV_SQRT_EMB = 0.08838834764831843f;
    float* gOut = out + (size_t)b * Pn * Nn;
    for (int pi = wid; pi < Pn / 2; pi += NWARP) {
        const int p0 = 2 * pi, p1 = p0 + 1;
        float s0[4], s1[4];
        int nn[4];
#pragma unroll
        for (int j = 0; j < 4; j++) {
            int n = lane + 32 * j;
            nn[j] = n;
            if (n < Nn) {
                s0[j] = tanh10(sQf[p0 * LDSR + n] * INV_SQRT_EMB) + gM[p0 * Nn + n];
                s1[j] = tanh10(sQf[p1 * LDSR + n] * INV_SQRT_EMB) + gM[p1 * Nn + n];
            } else { s0[j] = -INFINITY; s1[j] = -INFINITY; }
        }
        float mx0 = fmaxf(fmaxf(s0[0], s0[1]), fmaxf(s0[2], s0[3]));
        float mx1 = fmaxf(fmaxf(s1[0], s1[1]), fmaxf(s1[2], s1[3]));
#pragma unroll
        for (int off = 16; off; off >>= 1) {
            mx0 = fmaxf(mx0, __shfl_xor_sync(0xffffffffu, mx0, off));
            mx1 = fmaxf(mx1, __shfl_xor_sync(0xffffffffu, mx1, off));
        }
        float w0[4], w1[4], sum0 = 0.f, sum1 = 0.f;
#pragma unroll
        for (int j = 0; j < 4; j++) {
            w0[j] = __expf(s0[j] - mx0); sum0 += w0[j];
            w1[j] = __expf(s1[j] - mx1); sum1 += w1[j];
        }
#pragma unroll
        for (int off = 16; off; off >>= 1) {
            sum0 += __shfl_xor_sync(0xffffffffu, sum0, off);
            sum1 += __shfl_xor_sync(0xffffffffu, sum1, off);
        }
        const float inv0 = 1.f / sum0, inv1 = 1.f / sum1;
#pragma unroll
        for (int j = 0; j < 4; j++) {
            if (nn[j] < Nn) {
                gOut[p0 * Nn + nn[j]] = w0[j] * inv0;
                gOut[p1 * Nn + nn[j]] = w1[j] * inv1;
            }
        }
    }
}

extern "C" void kernel_launch(void* const* d_in, const int* in_sizes, int n_in,
                              void* d_out, int out_size) {
    const float* eln   = (const float*)d_in[0];
    const float* load_ = (const float*)d_in[1];
    const float* time_ = (const float*)d_in[2];
    const float* len_  = (const float*)d_in[3];
    const float* ropen = (const float*)d_in[4];
    const float* mask  = (const float*)d_in[5];
    const float* nodes = (const float*)d_in[6];
    const float* Wq    = (const float*)d_in[7];
    const float* Wk    = (const float*)d_in[8];
    const float* Wv    = (const float*)d_in[9];
    const float* Wc    = (const float*)d_in[10];
    const float* bc    = (const float*)d_in[11];
    float* out = (float*)d_out;

    prep_weights<<<4, 256>>>(Wq, Wk, Wv, Wc);
    cudaFuncSetAttribute(vrp_decoder_kernel,
                         cudaFuncAttributeMaxDynamicSharedMemorySize, SMEM_TOTAL);
    vrp_decoder_kernel<<<Bn, TPB, SMEM_TOTAL>>>(
        eln, load_, time_, len_, ropen, mask, nodes, bc, out);
}

// round 6
// speedup vs baseline: 1.7198x; 1.0170x over previous
#include <cuda_runtime.h>
#include <cuda_bf16.h>
#include <cstdint>

#define TPB 512
static constexpr int Bn = 1024, Pn = 100, Nn = 101, EMBn = 128;
static constexpr int Hn = 8, DKn = 16;

static constexpr int STB = 40;       // bf16 row stride inside chunk tiles (80B, conflict-free)
static constexpr int CHB = 10240;    // bytes per chunk matrix: 128 rows * 40 bf16 * 2B
// ---- smem byte map ----
static constexpr int SB_H = 0;              // B chunk hi (lo at +CHB)          20480B
static constexpr int SA_H = 20480;          // A chunk hi (lo at +CHB)          20480B
static constexpr int OFF_QF = 40960;        // Q / out_concat / scores [100][132] f32
static constexpr int OFF_KF = 93760;        // K / mh                  [101][132] f32
static constexpr int OFF_VF = 147088;       // V                       [101][132] f32
static constexpr int OFF_EX = 200416;       // extras [100][4] f32
static constexpr int OFF_WQ4 = 202016;      // Wq rows 128..131  [4][128] f32
static constexpr int OFF_BC = 204064;       // bc [128] f32
static constexpr int SMEM_TOTAL = 204576;
static constexpr int LDSR = 132;            // f32 row stride

// ---------------- prep: weights -> chunk-blocked bf16 hi/lo, B^T layout ----
__device__ __nv_bfloat16 g_wt[4][40960];
__device__ float g_wq4[512];

__global__ void prep_weights(const float* __restrict__ Wq, const float* __restrict__ Wk,
                             const float* __restrict__ Wv, const float* __restrict__ Wc)
{
    const int w = blockIdx.x;
    const float* W = (w == 0) ? Wq : (w == 1) ? Wk : (w == 2) ? Wv : Wc;
    for (int idx = threadIdx.x; idx < 128 * 128; idx += blockDim.x) {
        int n = idx >> 7, k = idx & 127;
        float x = W[k * 128 + n];
        __nv_bfloat16 h = __float2bfloat16(x);
        __nv_bfloat16 l = __float2bfloat16(x - __bfloat162float(h));
        int o = (k >> 5) * 10240 + n * STB + (k & 31);
        g_wt[w][o] = h;
        g_wt[w][o + 5120] = l;
    }
    if (w == 0) {
        for (int i = threadIdx.x; i < 512; i += blockDim.x)
            g_wq4[i] = Wq[128 * 128 + i];
    }
}

// ---------------- device helpers ----------------
__device__ __forceinline__ uint32_t smem_u32(const void* p) {
    uint32_t a;
    asm("{ .reg .u64 t; cvta.to.shared.u64 t, %1; cvt.u32.u64 %0, t; }" : "=r"(a) : "l"(p));
    return a;
}
__device__ __forceinline__ float tanh10(float x) {
    x = fminf(fmaxf(x, -20.f), 20.f);
    float t = __expf(2.f * x);
    return 10.f * (t - 1.f) / (t + 1.f);
}

#define LDSM4(R0, R1, R2, R3, ADDR) \
    asm volatile("ldmatrix.sync.aligned.m8n8.x4.shared.b16 {%0,%1,%2,%3}, [%4];" \
        : "=r"(R0), "=r"(R1), "=r"(R2), "=r"(R3) : "r"(ADDR))

#define MMA16816(C, A, B0, B1) \
    asm volatile("mma.sync.aligned.m16n8k16.row.col.f32.bf16.bf16.f32 " \
        "{%0,%1,%2,%3}, {%4,%5,%6,%7}, {%8,%9}, {%0,%1,%2,%3};" \
        : "+f"((C)[0]), "+f"((C)[1]), "+f"((C)[2]), "+f"((C)[3]) \
        : "r"((A)[0]), "r"((A)[1]), "r"((A)[2]), "r"((A)[3]), "r"(B0), "r"(B1))

// 32-value recursive-halving reduce-scatter.
template<int BASE>
__device__ __forceinline__ void reduce32(float* v, int lane) {
#pragma unroll
    for (int off = 16; off >= 1; off >>= 1) {
        const bool hi = (lane & off) != 0;
#pragma unroll
        for (int j = 0; j < 16; j++) {
            if (j < off) {
                float send = hi ? v[BASE + j] : v[BASE + j + off];
                float keep = hi ? v[BASE + j + off] : v[BASE + j];
                v[BASE + j] = keep + __shfl_xor_sync(0xffffffffu, send, off);
            }
        }
    }
}

// build one 128x32 hi/lo bf16 chunk from f32 row-major source
__device__ __forceinline__ void build_half(
    __nv_bfloat16* __restrict__ dst, const float* __restrict__ src,
    int ld, int nrows, int k0, const float* __restrict__ biasK)
{
    for (int i = threadIdx.x; i < 1024; i += TPB) {
        int r = i >> 3, q = (i & 7) << 2;
        float4 v = make_float4(0.f, 0.f, 0.f, 0.f);
        if (r < nrows) v = *(const float4*)&src[(size_t)r * ld + k0 + q];
        if (biasK) {
            v.x += biasK[k0 + q];     v.y += biasK[k0 + q + 1];
            v.z += biasK[k0 + q + 2]; v.w += biasK[k0 + q + 3];
        }
        __nv_bfloat162 h01 = __floats2bfloat162_rn(v.x, v.y);
        __nv_bfloat162 h23 = __floats2bfloat162_rn(v.z, v.w);
        __nv_bfloat162 l01 = __floats2bfloat162_rn(v.x - __bfloat162float(h01.x),
                                                   v.y - __bfloat162float(h01.y));
        __nv_bfloat162 l23 = __floats2bfloat162_rn(v.z - __bfloat162float(h23.x),
                                                   v.w - __bfloat162float(h23.y));
        int o = r * STB + q;
        *(__nv_bfloat162*)(dst + o)            = h01;
        *(__nv_bfloat162*)(dst + o + 2)        = h23;
        *(__nv_bfloat162*)(dst + 5120 + o)     = l01;
        *(__nv_bfloat162*)(dst + 5120 + o + 2) = l23;
    }
}

// C = A @ B via mma.sync, hi/lo split (3 products).
__device__ __noinline__ void gemm128(
    unsigned char* smem8, uint32_t sb,
    const float* __restrict__ Asrc, int Ald, int Anrows, const float* __restrict__ biasK,
    int wsel, const float* __restrict__ Bf32, int Bnrows,
    float* __restrict__ Cdst, int Cnrows)
{
    const int tid = threadIdx.x, w = tid >> 5, lane = tid & 31;
    const int wm = w & 3, wn = w >> 2;

    float acc[2][4][4];
#pragma unroll
    for (int m = 0; m < 2; m++)
#pragma unroll
        for (int n = 0; n < 4; n++)
#pragma unroll
            for (int j = 0; j < 4; j++) acc[m][n][j] = 0.f;

    for (int c = 0; c < 4; c++) {
        __syncthreads();
        const int k0 = c * 32;
        build_half((__nv_bfloat16*)(smem8 + SA_H), Asrc, Ald, Anrows, k0, biasK);
        if (wsel >= 0) {
            const uint4* src = (const uint4*)&g_wt[wsel][c * 10240];
            uint4* dst = (uint4*)(smem8 + SB_H);
            for (int i = tid; i < 1280; i += TPB) dst[i] = src[i];
        } else {
            build_half((__nv_bfloat16*)(smem8 + SB_H), Bf32, 128, Bnrows, k0, nullptr);
        }
        __syncthreads();

#pragma unroll
        for (int pass = 0; pass < 3; pass++) {
            const uint32_t Aoff = SA_H + (pass == 2 ? CHB : 0);
            const uint32_t Boff = SB_H + (pass == 1 ? CHB : 0);
#pragma unroll
            for (int ks = 0; ks < 2; ks++) {
                const int kb = ks * 16;
                uint32_t a[2][4];
#pragma unroll
                for (int m = 0; m < 2; m++) {
                    uint32_t addr = sb + Aoff +
                        (uint32_t)(((wm * 32 + m * 16 + (lane & 15)) * STB
                                    + kb + ((lane >> 4) << 3)) << 1);
                    LDSM4(a[m][0], a[m][1], a[m][2], a[m][3], addr);
                }
                uint32_t bfr[4][2];
#pragma unroll
                for (int t = 0; t < 2; t++) {
                    const int n0 = wn * 32 + t * 16;
                    uint32_t addr = sb + Boff +
                        (uint32_t)(((n0 + ((lane & 16) ? 8 : 0) + (lane & 7)) * STB
                                    + kb + ((lane & 8) ? 8 : 0)) << 1);
                    uint32_t r0, r1, r2, r3;
                    LDSM4(r0, r1, r2, r3, addr);
                    bfr[2 * t][0] = r0;     bfr[2 * t][1] = r1;
                    bfr[2 * t + 1][0] = r2; bfr[2 * t + 1][1] = r3;
                }
#pragma unroll
                for (int m = 0; m < 2; m++)
#pragma unroll
                    for (int n = 0; n < 4; n++)
                        MMA16816(acc[m][n], a[m], bfr[n][0], bfr[n][1]);
            }
        }
    }
    __syncthreads();
#pragma unroll
    for (int m = 0; m < 2; m++) {
#pragma unroll
        for (int n = 0; n < 4; n++) {
            const int row = wm * 32 + m * 16 + (lane >> 2);
            const int col = wn * 32 + n * 8 + ((lane & 3) << 1);
            if (row < Cnrows)
                *(float2*)&Cdst[row * LDSR + col] = make_float2(acc[m][n][0], acc[m][n][1]);
            if (row + 8 < Cnrows)
                *(float2*)&Cdst[(row + 8) * LDSR + col] = make_float2(acc[m][n][2], acc[m][n][3]);
        }
    }
    __syncthreads();
}

extern __shared__ __align__(16) unsigned char smem8[];

__global__ __launch_bounds__(TPB, 1)
void vrp_decoder_kernel(
    const float* __restrict__ eln,   const float* __restrict__ load_,
    const float* __restrict__ time_, const float* __restrict__ len_,
    const float* __restrict__ ropen, const float* __restrict__ mask,
    const float* __restrict__ nodes, const float* __restrict__ bc,
    float* __restrict__ out)
{
    const int b = blockIdx.x;
    const int tid = threadIdx.x;
    const int wid = tid >> 5, lane = tid & 31;
    const uint32_t sb = smem_u32(smem8);

    float* sQf  = (float*)(smem8 + OFF_QF);
    float* sKf  = (float*)(smem8 + OFF_KF);
    float* sVf  = (float*)(smem8 + OFF_VF);
    float* sEx  = (float*)(smem8 + OFF_EX);
    float* sWq4 = (float*)(smem8 + OFF_WQ4);
    float* sBc  = (float*)(smem8 + OFF_BC);

    // ---- stage aux ----
    for (int i = tid; i < 512; i += TPB) sWq4[i] = g_wq4[i];
    for (int i = tid; i < 128; i += TPB) sBc[i] = bc[i];
    for (int r = tid; r < Pn; r += TPB) {
        sEx[r * 4 + 0] = load_[b * Pn + r];
        sEx[r * 4 + 1] = time_[b * Pn + r];
        sEx[r * 4 + 2] = len_[b * Pn + r];
        sEx[r * 4 + 3] = ropen[b * Pn + r];
    }

    const float* gE = eln + (size_t)b * Pn * EMBn;
    const float* gN = nodes + (size_t)b * Nn * EMBn;

    // ---- Q = eln @ Wq[0:128] ----
    gemm128(smem8, sb, gE, EMBn, Pn, nullptr, 0, nullptr, 0, sQf, Pn);
    // 4-extra-feature correction
    for (int i = tid; i < Pn * 32; i += TPB) {
        int r = i >> 5, cq = (i & 31) << 2;
        float4 qv = *(float4*)&sQf[r * LDSR + cq];
        float e0 = sEx[r * 4 + 0], e1 = sEx[r * 4 + 1];
        float e2 = sEx[r * 4 + 2], e3 = sEx[r * 4 + 3];
        qv.x += e0 * sWq4[cq + 0] + e1 * sWq4[128 + cq + 0] + e2 * sWq4[256 + cq + 0] + e3 * sWq4[384 + cq + 0];
        qv.y += e0 * sWq4[cq + 1] + e1 * sWq4[128 + cq + 1] + e2 * sWq4[256 + cq + 1] + e3 * sWq4[384 + cq + 1];
        qv.z += e0 * sWq4[cq + 2] + e1 * sWq4[128 + cq + 2] + e2 * sWq4[256 + cq + 2] + e3 * sWq4[384 + cq + 2];
        qv.w += e0 * sWq4[cq + 3] + e1 * sWq4[128 + cq + 3] + e2 * sWq4[256 + cq + 3] + e3 * sWq4[384 + cq + 3];
        *(float4*)&sQf[r * LDSR + cq] = qv;
    }
    // ---- K, V = nodes @ Wk / Wv ----
    gemm128(smem8, sb, gN, EMBn, Nn, nullptr, 1, nullptr, 0, sKf, Nn);
    gemm128(smem8, sb, gN, EMBn, Nn, nullptr, 2, nullptr, 0, sVf, Nn);

    // ---- attention: work item = (4-row group, head): 25*8 = 200 items over 16 warps.
    // Item (g,h) is the sole reader AND writer of Q[4g..4g+3][16h..16h+15] -> in-place safe.
    const float* gM = mask + (size_t)b * Pn * Nn;
    const int NWARP = TPB / 32;
    for (int it = wid; it < 25 * Hn; it += NWARP) {
        const int g = it >> 3, h = it & 7;
        const int pb = g * 4;
        const int ho = h * DKn;
        // scores: s[r][j] for rows pb..pb+3, n = lane + 32j
        float s[4][4];
#pragma unroll
        for (int j = 0; j < 4; j++) {
            const int n = lane + 32 * j;
            const int ncj = n < Nn ? n : 0;
            const float* kr = &sKf[ncj * LDSR + ho];
            float4 k0 = *(const float4*)&kr[0],  k1 = *(const float4*)&kr[4];
            float4 k2 = *(const float4*)&kr[8],  k3 = *(const float4*)&kr[12];
#pragma unroll
            for (int r = 0; r < 4; r++) {
                const float* qr = &sQf[(pb + r) * LDSR + ho];
                float4 q0 = *(const float4*)&qr[0],  q1 = *(const float4*)&qr[4];
                float4 q2 = *(const float4*)&qr[8],  q3 = *(const float4*)&qr[12];
                float dot = q0.x * k0.x + q0.y * k0.y + q0.z * k0.z + q0.w * k0.w
                          + q1.x * k1.x + q1.y * k1.y + q1.z * k1.z + q1.w * k1.w
                          + q2.x * k2.x + q2.y * k2.y + q2.z * k2.z + q2.w * k2.w
                          + q3.x * k3.x + q3.y * k3.y + q3.z * k3.z + q3.w * k3.w;
                s[r][j] = (n < Nn) ? (dot * 0.25f + gM[(pb + r) * Nn + n]) : -INFINITY;
            }
        }
        // per-row softmax -> weights in place
#pragma unroll
        for (int r = 0; r < 4; r++) {
            float mx = fmaxf(fmaxf(s[r][0], s[r][1]), fmaxf(s[r][2], s[r][3]));
#pragma unroll
            for (int off = 16; off; off >>= 1)
                mx = fmaxf(mx, __shfl_xor_sync(0xffffffffu, mx, off));
            float sum = 0.f;
#pragma unroll
            for (int j = 0; j < 4; j++) { s[r][j] = __expf(s[r][j] - mx); sum += s[r][j]; }
#pragma unroll
            for (int off = 16; off; off >>= 1)
                sum += __shfl_xor_sync(0xffffffffu, sum, off);
            const float inv = 1.f / sum;
#pragma unroll
            for (int j = 0; j < 4; j++) s[r][j] *= inv;
        }
        // PV partials: v[r*16 + d]
        float v[64];
#pragma unroll
        for (int d = 0; d < 64; d++) v[d] = 0.f;
#pragma unroll
        for (int j = 0; j < 4; j++) {
            const int n = lane + 32 * j;
            const int ncj = n < Nn ? n : 0;
            const float* vr = &sVf[ncj * LDSR + ho];
            float4 v0 = *(const float4*)&vr[0],  v1 = *(const float4*)&vr[4];
            float4 v2 = *(const float4*)&vr[8],  v3 = *(const float4*)&vr[12];
#pragma unroll
            for (int r = 0; r < 4; r++) {
                const float wr = s[r][j];
                v[r * 16 + 0]  += wr * v0.x; v[r * 16 + 1]  += wr * v0.y;
                v[r * 16 + 2]  += wr * v0.z; v[r * 16 + 3]  += wr * v0.w;
                v[r * 16 + 4]  += wr * v1.x; v[r * 16 + 5]  += wr * v1.y;
                v[r * 16 + 6]  += wr * v1.z; v[r * 16 + 7]  += wr * v1.w;
                v[r * 16 + 8]  += wr * v2.x; v[r * 16 + 9]  += wr * v2.y;
                v[r * 16 + 10] += wr * v2.z; v[r * 16 + 11] += wr * v2.w;
                v[r * 16 + 12] += wr * v3.x; v[r * 16 + 13] += wr * v3.y;
                v[r * 16 + 14] += wr * v3.z; v[r * 16 + 15] += wr * v3.w;
            }
        }
        // two 32-value reduce-scatters
        reduce32<0>(v, lane);
        reduce32<32>(v, lane);
        {
            const int d = lane & 15;
            const int r = (lane < 16) ? 0 : 1;
            sQf[(pb + r) * LDSR + ho + d]     = v[0];
            sQf[(pb + 2 + r) * LDSR + ho + d] = v[32];
        }
    }

    // ---- mh = out_concat @ Wc; C -> sKf ----
    gemm128(smem8, sb, sQf, LDSR, Pn, nullptr, 3, nullptr, 0, sKf, Pn);
    // ---- score2 = (mh + bc) @ nodes^T; C -> sQf ----
    gemm128(smem8, sb, sKf, LDSR, Pn, sBc, -1, gN, Nn, sQf, Pn);

    // ---- final: clip*tanh(score2/sqrt(128)) + mask; softmax; store ----
    const float INV_SQRT_EMB = 0.08838834764831843f;
    float* gOut = out + (size_t)b * Pn * Nn;
    for (int pi = wid; pi < Pn / 2; pi += NWARP) {
        const int p0 = 2 * pi, p1 = p0 + 1;
        float s0[4], s1[4];
        int nn[4];
#pragma unroll
        for (int j = 0; j < 4; j++) {
            int n = lane + 32 * j;
            nn[j] = n;
            if (n < Nn) {
                s0[j] = tanh10(sQf[p0 * LDSR + n] * INV_SQRT_EMB) + gM[p0 * Nn + n];
                s1[j] = tanh10(sQf[p1 * LDSR + n] * INV_SQRT_EMB) + gM[p1 * Nn + n];
            } else { s0[j] = -INFINITY; s1[j] = -INFINITY; }
        }
        float mx0 = fmaxf(fmaxf(s0[0], s0[1]), fmaxf(s0[2], s0[3]));
        float mx1 = fmaxf(fmaxf(s1[0], s1[1]), fmaxf(s1[2], s1[3]));
#pragma unroll
        for (int off = 16; off; off >>= 1) {
            mx0 = fmaxf(mx0, __shfl_xor_sync(0xffffffffu, mx0, off));
            mx1 = fmaxf(mx1, __shfl_xor_sync(0xffffffffu, mx1, off));
        }
        float w0[4], w1[4], sum0 = 0.f, sum1 = 0.f;
#pragma unroll
        for (int j = 0; j < 4; j++) {
            w0[j] = __expf(s0[j] - mx0); sum0 += w0[j];
            w1[j] = __expf(s1[j] - mx1); sum1 += w1[j];
        }
#pragma unroll
        for (int off = 16; off; off >>= 1) {
            sum0 += __shfl_xor_sync(0xffffffffu, sum0, off);
            sum1 += __shfl_xor_sync(0xffffffffu, sum1, off);
        }
        const float inv0 = 1.f / sum0, inv1 = 1.f / sum1;
#pragma unroll
        for (int j = 0; j < 4; j++) {
            if (nn[j] < Nn) {
                gOut[p0 * Nn + nn[j]] = w0[j] * inv0;
                gOut[p1 * Nn + nn[j]] = w1[j] * inv1;
            }
        }
    }
}

extern "C" void kernel_launch(void* const* d_in, const int* in_sizes, int n_in,
                              void* d_out, int out_size) {
    const float* eln   = (const float*)d_in[0];
    const float* load_ = (const float*)d_in[1];
    const float* time_ = (const float*)d_in[2];
    const float* len_  = (const float*)d_in[3];
    const float* ropen = (const float*)d_in[4];
    const float* mask  = (const float*)d_in[5];
    const float* nodes = (const float*)d_in[6];
    const float* Wq    = (const float*)d_in[7];
    const float* Wk    = (const float*)d_in[8];
    const float* Wv    = (const float*)d_in[9];
    const float* Wc    = (const float*)d_in[10];
    const float* bc    = (const float*)d_in[11];
    float* out = (float*)d_out;

    prep_weights<<<4, 256>>>(Wq, Wk, Wv, Wc);
    cudaFuncSetAttribute(vrp_decoder_kernel,
                         cudaFuncAttributeMaxDynamicSharedMemorySize, SMEM_TOTAL);
    vrp_decoder_kernel<<<Bn, TPB, SMEM_TOTAL>>>(
        eln, load_, time_, len_, ropen, mask, nodes, bc, out);
}